// round 5
// baseline (speedup 1.0000x reference)
#include <cuda_runtime.h>

#define N_NODES 50000
#define N_EDGES 800000
#define D 64
#define MEAN_BLOCKS 256

// ---------------- scratch (static device memory; no allocs) ----------------
__device__ float g_h [N_NODES * D];   // h = x @ W (pre-aggregation)
__device__ float g_xa[N_NODES * D];   // ping
__device__ float g_xb[N_NODES * D];   // pong
__device__ float g_deg [N_NODES];
__device__ float g_dinv[N_NODES];
__device__ int   g_esrc[N_EDGES];
__device__ int   g_edst[N_EDGES];
__device__ float g_enrm[N_EDGES];
__device__ float g_partial[MEAN_BLOCKS * D];
__device__ int   g_is64;              // edge_index dtype flag

__device__ __forceinline__ float* selbuf(int s) { return (s == 0) ? g_xa : g_xb; }

// ---------------- dtype detect: int64 indices < 50000 have all-zero high words
__global__ void k_detect(const int* __restrict__ ei32) {
    __shared__ int bad;
    if (threadIdx.x == 0) bad = 0;
    __syncthreads();
    for (int i = threadIdx.x; i < 1024; i += blockDim.x)
        if (ei32[2 * i + 1] != 0) bad = 1;   // racy write: any-nonzero is enough
    __syncthreads();
    if (threadIdx.x == 0) g_is64 = bad ? 0 : 1;
}

// ---------------- edge convert: -> int32 src/dst, clamped (trap-proof) ------
__global__ void k_edges(const void* __restrict__ ei) {
    int e = blockIdx.x * blockDim.x + threadIdx.x;
    if (e >= N_EDGES) return;
    int s, d;
    if (g_is64) {
        const long long* p = (const long long*)ei;
        s = (int)p[e];
        d = (int)p[N_EDGES + e];
    } else {
        const int* p = (const int*)ei;
        s = p[e];
        d = p[N_EDGES + e];
    }
    s = min(max(s, 0), N_NODES - 1);
    d = min(max(d, 0), N_NODES - 1);
    g_esrc[e] = s;
    g_edst[e] = d;
}

// ---------------- init: deg = 1 (self-loop) ----------------
__global__ void k_init() {
    int i = blockIdx.x * blockDim.x + threadIdx.x;
    if (i < N_NODES) g_deg[i] = 1.0f;
}

// ---------------- degree: deg[dst] += 1 over edges ----------------
__global__ void k_deg() {
    int e = blockIdx.x * blockDim.x + threadIdx.x;
    if (e < N_EDGES) atomicAdd(&g_deg[g_edst[e]], 1.0f);
}

__global__ void k_dinv() {
    int i = blockIdx.x * blockDim.x + threadIdx.x;
    if (i < N_NODES) g_dinv[i] = rsqrtf(g_deg[i]);
}

// ---------------- per-edge norm ----------------
__global__ void k_norm() {
    int e = blockIdx.x * blockDim.x + threadIdx.x;
    if (e < N_EDGES) g_enrm[e] = g_dinv[g_esrc[e]] * g_dinv[g_edst[e]];
}

// ---------------- GEMM + self-loop/bias epilogue ----------------
// h = xin @ W ; out = h * dinv^2 + b
// 16 rows per block, 256 threads: thread = (rowgroup, col), 4 rows each.
__global__ void k_gemm(int in_sel, int out_sel,
                       const float* __restrict__ x0,
                       const float* __restrict__ W,
                       const float* __restrict__ b) {
    const float* xin = (in_sel < 0) ? x0 : (const float*)selbuf(in_sel);
    float* out = (float*)selbuf(out_sel);

    __shared__ float Ws[64 * 64];
    __shared__ float xs[16 * 64];

    int tid = threadIdx.x;
    #pragma unroll
    for (int i = tid; i < 64 * 64; i += 256) Ws[i] = W[i];
    int row0 = blockIdx.x * 16;
    #pragma unroll
    for (int i = tid; i < 16 * 64; i += 256) xs[i] = xin[row0 * 64 + i];
    __syncthreads();

    int j  = tid & 63;          // output column (consecutive in warp)
    int rb = (tid >> 6) * 4;    // first of 4 rows for this thread

    float a0 = 0.f, a1 = 0.f, a2 = 0.f, a3 = 0.f;
    #pragma unroll
    for (int k = 0; k < 64; k++) {
        float w = Ws[k * 64 + j];
        a0 += xs[(rb + 0) * 64 + k] * w;
        a1 += xs[(rb + 1) * 64 + k] * w;
        a2 += xs[(rb + 2) * 64 + k] * w;
        a3 += xs[(rb + 3) * 64 + k] * w;
    }
    float bj = b[j];
    float accs[4] = {a0, a1, a2, a3};
    #pragma unroll
    for (int r = 0; r < 4; r++) {
        int row = row0 + rb + r;
        float di = g_dinv[row];
        g_h[row * 64 + j] = accs[r];
        out[row * 64 + j] = accs[r] * di * di + bj;   // self-loop msg + bias
    }
}

// ---------------- edge scatter: out[dst] += h[src] * norm --------------------
// 64 threads per edge (one per column). Per warp: one 128B gather segment and
// one 128B RED segment.
__global__ void k_scatter(int out_sel) {
    int id = blockIdx.x * blockDim.x + threadIdx.x;
    int e = id >> 6;
    int c = id & 63;
    if (e >= N_EDGES) return;
    int   s = g_esrc[e];
    int   d = g_edst[e];
    float n = g_enrm[e];
    float v = __ldg(&g_h[s * 64 + c]) * n;
    atomicAdd(&selbuf(out_sel)[d * 64 + c], v);
}

// ---------------- column mean, two stage, no atomics on d_out ----------------
__global__ void k_mean_partial(int in_sel) {
    const float* x = (const float*)selbuf(in_sel);
    int t = threadIdx.x;   // 64 threads = 64 columns
    float s = 0.f;
    for (int r = blockIdx.x; r < N_NODES; r += MEAN_BLOCKS) s += x[r * 64 + t];
    g_partial[blockIdx.x * 64 + t] = s;
}

__global__ void k_mean_final(float* __restrict__ out, int off) {
    int t = threadIdx.x;   // 64 threads
    float s = 0.f;
    #pragma unroll 8
    for (int b = 0; b < MEAN_BLOCKS; b++) s += g_partial[b * 64 + t];
    out[off + t] = s * (1.0f / (float)N_NODES);
}

// ---------------- launch ----------------
extern "C" void kernel_launch(void* const* d_in, const int* in_sizes, int n_in,
                              void* d_out, int out_size) {
    const float* x   = (const float*)d_in[0];
    const void*  ei  = d_in[1];
    float*       out = (float*)d_out;

    k_detect<<<1, 256>>>((const int*)ei);
    k_edges <<<(N_EDGES + 255) / 256, 256>>>(ei);
    k_init  <<<(N_NODES + 255) / 256, 256>>>();
    k_deg   <<<(N_EDGES + 255) / 256, 256>>>();
    k_dinv  <<<(N_NODES + 255) / 256, 256>>>();
    k_norm  <<<(N_EDGES + 255) / 256, 256>>>();

    for (int l = 0; l < 4; l++) {
        int in_sel  = (l == 0) ? -1 : ((l - 1) & 1);
        int out_sel = l & 1;
        const float* W = (const float*)d_in[2 + 2 * l];
        const float* b = (const float*)d_in[3 + 2 * l];
        k_gemm<<<N_NODES / 16, 256>>>(in_sel, out_sel, x, W, b);
        k_scatter<<<(N_EDGES * 64) / 256, 256>>>(out_sel);
        k_mean_partial<<<MEAN_BLOCKS, 64>>>(out_sel);
        k_mean_final<<<1, 64>>>(out, l * D);
    }
}

// round 6
// speedup vs baseline: 1.8335x; 1.8335x over previous
#include <cuda_runtime.h>

#define N_NODES 50000
#define N_EDGES 800000
#define D 64
#define MEAN_BLOCKS 256
#define SCAN_B 256
#define SCAN_NBLK ((N_NODES + SCAN_B - 1) / SCAN_B)   // 196

// ---------------- scratch (static device memory; no allocs) ----------------
__device__ float g_h [N_NODES * D];   // h = x @ W (pre-aggregation)
__device__ float g_xa[N_NODES * D];   // ping
__device__ float g_xb[N_NODES * D];   // pong
__device__ float g_dinv[N_NODES];
__device__ int   g_cnt [N_NODES];     // in-degree histogram (excl. self-loop)
__device__ int   g_cur [N_NODES];     // fill cursors
__device__ int   g_rowptr[N_NODES];   // exclusive prefix of g_cnt
__device__ int   g_esrc[N_EDGES];
__device__ int   g_edst[N_EDGES];
__device__ int   g_csr_src[N_EDGES];  // dst-sorted sources
__device__ float g_csr_nrm[N_EDGES];  // matching edge weights
__device__ int   g_blocksum[SCAN_NBLK];
__device__ float g_partial[MEAN_BLOCKS * D];
__device__ int   g_is64;              // edge_index dtype flag

__device__ __forceinline__ float* selbuf(int s) { return (s == 0) ? g_xa : g_xb; }

// ---------------- dtype detect: int64 indices < 50000 have all-zero high words
__global__ void k_detect(const int* __restrict__ ei32) {
    __shared__ int bad;
    if (threadIdx.x == 0) bad = 0;
    __syncthreads();
    for (int i = threadIdx.x; i < 1024; i += blockDim.x)
        if (ei32[2 * i + 1] != 0) bad = 1;
    __syncthreads();
    if (threadIdx.x == 0) g_is64 = bad ? 0 : 1;
}

// ---------------- zero counters ----------------
__global__ void k_zero() {
    int i = blockIdx.x * blockDim.x + threadIdx.x;
    if (i < N_NODES) { g_cnt[i] = 0; g_cur[i] = 0; }
}

// ---------------- edge convert (clamped) + in-degree histogram --------------
__global__ void k_edges(const void* __restrict__ ei) {
    int e = blockIdx.x * blockDim.x + threadIdx.x;
    if (e >= N_EDGES) return;
    int s, d;
    if (g_is64) {
        const long long* p = (const long long*)ei;
        s = (int)p[e];
        d = (int)p[N_EDGES + e];
    } else {
        const int* p = (const int*)ei;
        s = p[e];
        d = p[N_EDGES + e];
    }
    s = min(max(s, 0), N_NODES - 1);
    d = min(max(d, 0), N_NODES - 1);
    g_esrc[e] = s;
    g_edst[e] = d;
    atomicAdd(&g_cnt[d], 1);
}

// ---------------- dinv from histogram (+1 self-loop) ----------------
__global__ void k_dinv() {
    int i = blockIdx.x * blockDim.x + threadIdx.x;
    if (i < N_NODES) g_dinv[i] = rsqrtf(1.0f + (float)g_cnt[i]);
}

// ---------------- 3-kernel exclusive scan of g_cnt -> g_rowptr --------------
__global__ void k_scan1() {
    __shared__ int sh[SCAN_B];
    int b = blockIdx.x, t = threadIdx.x;
    int i = b * SCAN_B + t;
    int v = (i < N_NODES) ? g_cnt[i] : 0;
    sh[t] = v;
    __syncthreads();
    // Hillis-Steele inclusive scan
    for (int off = 1; off < SCAN_B; off <<= 1) {
        int add = (t >= off) ? sh[t - off] : 0;
        __syncthreads();
        sh[t] += add;
        __syncthreads();
    }
    if (i < N_NODES) g_rowptr[i] = sh[t] - v;   // exclusive
    if (t == SCAN_B - 1) g_blocksum[b] = sh[t];
}

__global__ void k_scan2() {   // single block scans block sums (196 <= 256)
    __shared__ int sh[SCAN_B];
    int t = threadIdx.x;
    int v = (t < SCAN_NBLK) ? g_blocksum[t] : 0;
    sh[t] = v;
    __syncthreads();
    for (int off = 1; off < SCAN_B; off <<= 1) {
        int add = (t >= off) ? sh[t - off] : 0;
        __syncthreads();
        sh[t] += add;
        __syncthreads();
    }
    if (t < SCAN_NBLK) g_blocksum[t] = sh[t] - v;   // exclusive
}

__global__ void k_scan3() {
    int i = blockIdx.x * blockDim.x + threadIdx.x;
    if (i < N_NODES) g_rowptr[i] += g_blocksum[blockIdx.x * blockDim.x / SCAN_B == 0 ? 0 : 0];   // placeholder avoided below
}

// (k_scan3 proper: add block offset; blockDim 256 aligned with scan tiles)
__global__ void k_scan3b() {
    int i = blockIdx.x * SCAN_B + threadIdx.x;
    if (i < N_NODES) g_rowptr[i] += g_blocksum[blockIdx.x];
}

// ---------------- CSR fill: dst-sorted (src, norm) ----------------
__global__ void k_fill() {
    int e = blockIdx.x * blockDim.x + threadIdx.x;
    if (e >= N_EDGES) return;
    int s = g_esrc[e];
    int d = g_edst[e];
    int pos = g_rowptr[d] + atomicAdd(&g_cur[d], 1);
    g_csr_src[pos] = s;
    g_csr_nrm[pos] = g_dinv[s] * g_dinv[d];
}

// ---------------- GEMM: h = xin @ W (h only; epilogue moved to k_aggr) ------
__global__ void k_gemm(int in_sel,
                       const float* __restrict__ x0,
                       const float* __restrict__ W) {
    const float* xin = (in_sel < 0) ? x0 : (const float*)selbuf(in_sel);

    __shared__ float Ws[64 * 64];
    __shared__ float xs[16 * 64];

    int tid = threadIdx.x;
    #pragma unroll
    for (int i = tid; i < 64 * 64; i += 256) Ws[i] = W[i];
    int row0 = blockIdx.x * 16;
    #pragma unroll
    for (int i = tid; i < 16 * 64; i += 256) xs[i] = xin[row0 * 64 + i];
    __syncthreads();

    int j  = tid & 63;
    int rb = (tid >> 6) * 4;

    float a0 = 0.f, a1 = 0.f, a2 = 0.f, a3 = 0.f;
    #pragma unroll
    for (int k = 0; k < 64; k++) {
        float w = Ws[k * 64 + j];
        a0 += xs[(rb + 0) * 64 + k] * w;
        a1 += xs[(rb + 1) * 64 + k] * w;
        a2 += xs[(rb + 2) * 64 + k] * w;
        a3 += xs[(rb + 3) * 64 + k] * w;
    }
    g_h[(row0 + rb + 0) * 64 + j] = a0;
    g_h[(row0 + rb + 1) * 64 + j] = a1;
    g_h[(row0 + rb + 2) * 64 + j] = a2;
    g_h[(row0 + rb + 3) * 64 + j] = a3;
}

// ---------------- pull aggregation: out[d] = sum_in h[s]*nrm + self + bias --
// 64 threads per node (one per column); no atomics anywhere.
__global__ void k_aggr(int out_sel, const float* __restrict__ b) {
    int id = blockIdx.x * blockDim.x + threadIdx.x;
    int node = id >> 6;
    int c    = id & 63;
    if (node >= N_NODES) return;
    float* out = selbuf(out_sel);

    float di  = g_dinv[node];
    float acc = g_h[node * 64 + c] * di * di;     // self-loop message

    int beg = g_rowptr[node];
    int end = (node == N_NODES - 1) ? N_EDGES : g_rowptr[node + 1];

    int i = beg;
    for (; i + 1 < end; i += 2) {                 // 2x unroll for gather MLP
        int   s0 = __ldg(&g_csr_src[i]);
        int   s1 = __ldg(&g_csr_src[i + 1]);
        float n0 = __ldg(&g_csr_nrm[i]);
        float n1 = __ldg(&g_csr_nrm[i + 1]);
        acc += __ldg(&g_h[s0 * 64 + c]) * n0;
        acc += __ldg(&g_h[s1 * 64 + c]) * n1;
    }
    if (i < end) {
        int   s0 = __ldg(&g_csr_src[i]);
        float n0 = __ldg(&g_csr_nrm[i]);
        acc += __ldg(&g_h[s0 * 64 + c]) * n0;
    }
    out[node * 64 + c] = acc + b[c];
}

// ---------------- column mean, two stage, no atomics on d_out ----------------
__global__ void k_mean_partial(int in_sel) {
    const float* x = (const float*)selbuf(in_sel);
    int t = threadIdx.x;
    float s = 0.f;
    for (int r = blockIdx.x; r < N_NODES; r += MEAN_BLOCKS) s += x[r * 64 + t];
    g_partial[blockIdx.x * 64 + t] = s;
}

__global__ void k_mean_final(float* __restrict__ out, int off) {
    int t = threadIdx.x;
    float s = 0.f;
    #pragma unroll 8
    for (int b = 0; b < MEAN_BLOCKS; b++) s += g_partial[b * 64 + t];
    out[off + t] = s * (1.0f / (float)N_NODES);
}

// ---------------- launch ----------------
extern "C" void kernel_launch(void* const* d_in, const int* in_sizes, int n_in,
                              void* d_out, int out_size) {
    const float* x   = (const float*)d_in[0];
    const void*  ei  = d_in[1];
    float*       out = (float*)d_out;

    k_detect<<<1, 256>>>((const int*)ei);
    k_zero  <<<(N_NODES + 255) / 256, 256>>>();
    k_edges <<<(N_EDGES + 255) / 256, 256>>>(ei);
    k_dinv  <<<(N_NODES + 255) / 256, 256>>>();
    k_scan1 <<<SCAN_NBLK, SCAN_B>>>();
    k_scan2 <<<1, SCAN_B>>>();
    k_scan3b<<<SCAN_NBLK, SCAN_B>>>();
    k_fill  <<<(N_EDGES + 255) / 256, 256>>>();

    for (int l = 0; l < 4; l++) {
        int in_sel  = (l == 0) ? -1 : ((l - 1) & 1);
        int out_sel = l & 1;
        const float* W = (const float*)d_in[2 + 2 * l];
        const float* b = (const float*)d_in[3 + 2 * l];
        k_gemm<<<N_NODES / 16, 256>>>(in_sel, x, W);
        k_aggr<<<(N_NODES * 64 + 255) / 256, 256>>>(out_sel, b);
        k_mean_partial<<<MEAN_BLOCKS, 64>>>(out_sel);
        k_mean_final<<<1, 64>>>(out, l * D);
    }
}

// round 7
// speedup vs baseline: 3.0608x; 1.6693x over previous
#include <cuda_runtime.h>

#define N_NODES 50000
#define N_EDGES 800000
#define D 64
#define SCAN_B 256
#define SCAN_NBLK ((N_NODES + SCAN_B - 1) / SCAN_B)   // 196
#define MEAN_SPREAD 8

// ---------------- scratch (static device memory; no allocs) ----------------
__device__ float g_h [N_NODES * D];   // h = x @ W (pre-aggregation)
__device__ float g_xa[N_NODES * D];   // ping
__device__ float g_xb[N_NODES * D];   // pong
__device__ float g_dinv[N_NODES];
__device__ int   g_cnt [N_NODES];     // in-degree histogram (excl. self-loop)
__device__ int   g_cur [N_NODES];     // fill cursors
__device__ int   g_rowptr[N_NODES];   // exclusive prefix of g_cnt
__device__ int   g_esrc[N_EDGES];
__device__ int   g_edst[N_EDGES];
__device__ int2  g_csr[N_EDGES];      // dst-sorted (src, nrm-bits)
__device__ int   g_blocksum[SCAN_NBLK];
__device__ float g_meanacc[4 * MEAN_SPREAD * D];   // fused mean buckets
__device__ int   g_is64;

__device__ __forceinline__ float* selbuf(int s) { return (s == 0) ? g_xa : g_xb; }

// ---------------- dtype detect: int64 indices < 50000 have all-zero high words
__global__ void k_detect(const int* __restrict__ ei32) {
    __shared__ int bad;
    if (threadIdx.x == 0) bad = 0;
    __syncthreads();
    for (int i = threadIdx.x; i < 1024; i += blockDim.x)
        if (ei32[2 * i + 1] != 0) bad = 1;
    __syncthreads();
    if (threadIdx.x == 0) g_is64 = bad ? 0 : 1;
}

// ---------------- zero counters + mean buckets ----------------
__global__ void k_zero() {
    int i = blockIdx.x * blockDim.x + threadIdx.x;
    if (i < N_NODES) { g_cnt[i] = 0; g_cur[i] = 0; }
    if (i < 4 * MEAN_SPREAD * D) g_meanacc[i] = 0.f;
}

// ---------------- edge convert (clamped) + in-degree histogram --------------
__global__ void k_edges(const void* __restrict__ ei) {
    int e = blockIdx.x * blockDim.x + threadIdx.x;
    if (e >= N_EDGES) return;
    int s, d;
    if (g_is64) {
        const long long* p = (const long long*)ei;
        s = (int)p[e];
        d = (int)p[N_EDGES + e];
    } else {
        const int* p = (const int*)ei;
        s = p[e];
        d = p[N_EDGES + e];
    }
    s = min(max(s, 0), N_NODES - 1);
    d = min(max(d, 0), N_NODES - 1);
    g_esrc[e] = s;
    g_edst[e] = d;
    atomicAdd(&g_cnt[d], 1);
}

// ---------------- dinv from histogram (+1 self-loop) ----------------
__global__ void k_dinv() {
    int i = blockIdx.x * blockDim.x + threadIdx.x;
    if (i < N_NODES) g_dinv[i] = rsqrtf(1.0f + (float)g_cnt[i]);
}

// ---------------- 3-kernel exclusive scan of g_cnt -> g_rowptr --------------
__global__ void k_scan1() {
    __shared__ int sh[SCAN_B];
    int b = blockIdx.x, t = threadIdx.x;
    int i = b * SCAN_B + t;
    int v = (i < N_NODES) ? g_cnt[i] : 0;
    sh[t] = v;
    __syncthreads();
    for (int off = 1; off < SCAN_B; off <<= 1) {
        int add = (t >= off) ? sh[t - off] : 0;
        __syncthreads();
        sh[t] += add;
        __syncthreads();
    }
    if (i < N_NODES) g_rowptr[i] = sh[t] - v;
    if (t == SCAN_B - 1) g_blocksum[b] = sh[t];
}

__global__ void k_scan2() {
    __shared__ int sh[SCAN_B];
    int t = threadIdx.x;
    int v = (t < SCAN_NBLK) ? g_blocksum[t] : 0;
    sh[t] = v;
    __syncthreads();
    for (int off = 1; off < SCAN_B; off <<= 1) {
        int add = (t >= off) ? sh[t - off] : 0;
        __syncthreads();
        sh[t] += add;
        __syncthreads();
    }
    if (t < SCAN_NBLK) g_blocksum[t] = sh[t] - v;
}

__global__ void k_scan3() {
    int i = blockIdx.x * SCAN_B + threadIdx.x;
    if (i < N_NODES) g_rowptr[i] += g_blocksum[blockIdx.x];
}

// ---------------- CSR fill: dst-sorted packed (src, norm) ----------------
__global__ void k_fill() {
    int e = blockIdx.x * blockDim.x + threadIdx.x;
    if (e >= N_EDGES) return;
    int s = g_esrc[e];
    int d = g_edst[e];
    int pos = g_rowptr[d] + atomicAdd(&g_cur[d], 1);
    g_csr[pos] = make_int2(s, __float_as_int(g_dinv[s] * g_dinv[d]));
}

// ---------------- GEMM: h = xin @ W (32 rows/block, 8 rows/thread) ----------
__global__ void k_gemm(int in_sel,
                       const float* __restrict__ x0,
                       const float* __restrict__ W) {
    const float* xin = (in_sel < 0) ? x0 : (const float*)selbuf(in_sel);

    __shared__ float Ws[64 * 64];
    __shared__ float xs[32 * 64];

    int tid = threadIdx.x;
    #pragma unroll
    for (int i = tid; i < 64 * 64; i += 256) Ws[i] = W[i];
    int row0 = blockIdx.x * 32;
    #pragma unroll
    for (int i = tid; i < 32 * 64; i += 256) {
        int r = row0 + (i >> 6);
        xs[i] = (r < N_NODES) ? xin[r * 64 + (i & 63)] : 0.f;
    }
    __syncthreads();

    int j  = tid & 63;          // output column
    int rb = (tid >> 6) * 8;    // first of 8 rows for this thread

    float acc[8] = {0.f, 0.f, 0.f, 0.f, 0.f, 0.f, 0.f, 0.f};
    #pragma unroll
    for (int k = 0; k < 64; k++) {
        float w = Ws[k * 64 + j];
        #pragma unroll
        for (int r = 0; r < 8; r++) acc[r] += xs[(rb + r) * 64 + k] * w;
    }
    #pragma unroll
    for (int r = 0; r < 8; r++) {
        int row = row0 + rb + r;
        if (row < N_NODES) g_h[row * 64 + j] = acc[r];
    }
}

// ---------------- pull aggregation + fused mean ------------------------------
// 16 threads/node, float4 columns. Warp covers 2 nodes; loop to warp-max len
// with predicated lanes. No atomics on node data; mean via block reduction.
__global__ void k_aggr(int out_sel, int layer, const float4* __restrict__ b4p) {
    int id   = blockIdx.x * 256 + threadIdx.x;
    int node = id >> 4;
    int c4   = id & 15;
    const float4* h4  = (const float4*)g_h;
    float4*       out4 = (float4*)selbuf(out_sel);

    float di = g_dinv[node];
    float sl = di * di;
    float4 acc = h4[node * 16 + c4];          // self-loop message
    acc.x *= sl; acc.y *= sl; acc.z *= sl; acc.w *= sl;

    int beg = g_rowptr[node];
    int end = (node == N_NODES - 1) ? N_EDGES : g_rowptr[node + 1];
    int len = end - beg;
    int m   = max(len, __shfl_xor_sync(0xffffffffu, len, 16));

    for (int j = 0; j < m; j += 2) {
        int2 e0, e1;
        float4 v0, v1;
        bool p0 = (j < len), p1 = (j + 1 < len);
        if (p0) e0 = __ldg(&g_csr[beg + j]);
        if (p1) e1 = __ldg(&g_csr[beg + j + 1]);
        if (p0) v0 = __ldg(&h4[e0.x * 16 + c4]);
        if (p1) v1 = __ldg(&h4[e1.x * 16 + c4]);
        if (p0) {
            float n = __int_as_float(e0.y);
            acc.x += v0.x * n; acc.y += v0.y * n;
            acc.z += v0.z * n; acc.w += v0.w * n;
        }
        if (p1) {
            float n = __int_as_float(e1.y);
            acc.x += v1.x * n; acc.y += v1.y * n;
            acc.z += v1.z * n; acc.w += v1.w * n;
        }
    }
    float4 bv = __ldg(&b4p[c4]);
    acc.x += bv.x; acc.y += bv.y; acc.z += bv.z; acc.w += bv.w;
    out4[node * 16 + c4] = acc;

    // fused column-mean: reduce 16 nodes of this block, spread-atomic to scratch
    __shared__ float4 sh[256];
    int t = threadIdx.x;
    sh[t] = acc;
    __syncthreads();
    if (t < 128) { sh[t].x += sh[t+128].x; sh[t].y += sh[t+128].y;
                   sh[t].z += sh[t+128].z; sh[t].w += sh[t+128].w; }
    __syncthreads();
    if (t < 64)  { sh[t].x += sh[t+64].x; sh[t].y += sh[t+64].y;
                   sh[t].z += sh[t+64].z; sh[t].w += sh[t+64].w; }
    __syncthreads();
    if (t < 32)  { sh[t].x += sh[t+32].x; sh[t].y += sh[t+32].y;
                   sh[t].z += sh[t+32].z; sh[t].w += sh[t+32].w; }
    __syncthreads();
    if (t < 16) {
        float4 s = sh[t];
        s.x += sh[t+16].x; s.y += sh[t+16].y; s.z += sh[t+16].z; s.w += sh[t+16].w;
        float* gp = &g_meanacc[(layer * MEAN_SPREAD + (blockIdx.x & (MEAN_SPREAD - 1))) * D + t * 4];
        atomicAdd(&gp[0], s.x);
        atomicAdd(&gp[1], s.y);
        atomicAdd(&gp[2], s.z);
        atomicAdd(&gp[3], s.w);
    }
}

// ---------------- finish: reduce mean buckets for all 4 layers ----------------
__global__ void k_finish(float* __restrict__ out) {
    int t = threadIdx.x;          // 256 threads: layer = t>>6, col = t&63
    int layer = t >> 6;
    int c = t & 63;
    float s = 0.f;
    #pragma unroll
    for (int k = 0; k < MEAN_SPREAD; k++)
        s += g_meanacc[(layer * MEAN_SPREAD + k) * D + c];
    out[layer * D + c] = s * (1.0f / (float)N_NODES);
}

// ---------------- launch ----------------
extern "C" void kernel_launch(void* const* d_in, const int* in_sizes, int n_in,
                              void* d_out, int out_size) {
    const float* x   = (const float*)d_in[0];
    const void*  ei  = d_in[1];
    float*       out = (float*)d_out;

    k_detect<<<1, 256>>>((const int*)ei);
    k_zero  <<<(N_NODES + 255) / 256, 256>>>();
    k_edges <<<(N_EDGES + 255) / 256, 256>>>(ei);
    k_dinv  <<<(N_NODES + 255) / 256, 256>>>();
    k_scan1 <<<SCAN_NBLK, SCAN_B>>>();
    k_scan2 <<<1, SCAN_B>>>();
    k_scan3 <<<SCAN_NBLK, SCAN_B>>>();
    k_fill  <<<(N_EDGES + 255) / 256, 256>>>();

    for (int l = 0; l < 4; l++) {
        int in_sel  = (l == 0) ? -1 : ((l - 1) & 1);
        int out_sel = l & 1;
        const float* W = (const float*)d_in[2 + 2 * l];
        const float* b = (const float*)d_in[3 + 2 * l];
        k_gemm<<<(N_NODES + 31) / 32, 256>>>(in_sel, x, W);
        k_aggr<<<(N_NODES * 16) / 256, 256>>>(out_sel, l, (const float4*)b);
    }
    k_finish<<<1, 256>>>(out);
}

// round 8
// speedup vs baseline: 3.5049x; 1.1451x over previous
#include <cuda_runtime.h>

#define N_NODES 50000
#define N_EDGES 800000
#define D 64
#define SCAN_B 256
#define SCAN_NBLK ((N_NODES + SCAN_B - 1) / SCAN_B)   // 196
#define MEAN_SPREAD 8

// ---------------- scratch (static device memory; no allocs) ----------------
__device__ float g_h [N_NODES * D];   // h = x @ W (pre-aggregation)
__device__ float g_xa[N_NODES * D];   // ping
__device__ float g_xb[N_NODES * D];   // pong
__device__ float g_dinv[N_NODES];
__device__ int   g_cnt [N_NODES];     // in-degree histogram (excl. self-loop)
__device__ int   g_cur [N_NODES];     // fill cursors
__device__ int   g_rowptr[N_NODES];   // block-local exclusive prefix of g_cnt
__device__ int   g_esrc[N_EDGES];
__device__ int   g_edst[N_EDGES];
__device__ int2  g_csr[N_EDGES];      // dst-sorted (src, nrm-bits)
__device__ int   g_blocksum[SCAN_NBLK];   // exclusive block offsets
__device__ float g_meanacc[4 * MEAN_SPREAD * D];
__device__ int   g_is64;

__device__ __forceinline__ float* selbuf(int s) { return (s == 0) ? g_xa : g_xb; }

// ---------------- zero counters + mean buckets; dtype detect in block 0 -----
__global__ void k_zero(const int* __restrict__ ei32) {
    int i = blockIdx.x * blockDim.x + threadIdx.x;
    if (i < N_NODES) { g_cnt[i] = 0; g_cur[i] = 0; }
    if (i < 4 * MEAN_SPREAD * D) g_meanacc[i] = 0.f;
    if (blockIdx.x == 0) {
        __shared__ int bad;
        if (threadIdx.x == 0) bad = 0;
        __syncthreads();
        for (int t = threadIdx.x; t < 1024; t += blockDim.x)
            if (ei32[2 * t + 1] != 0) bad = 1;   // int32 random data -> nonzero
        __syncthreads();
        if (threadIdx.x == 0) g_is64 = bad ? 0 : 1;
    }
}

// ---------------- edge convert (clamped) + in-degree histogram --------------
__global__ void k_edges(const void* __restrict__ ei) {
    int e = blockIdx.x * blockDim.x + threadIdx.x;
    if (e >= N_EDGES) return;
    int s, d;
    if (g_is64) {
        const long long* p = (const long long*)ei;
        s = (int)p[e];
        d = (int)p[N_EDGES + e];
    } else {
        const int* p = (const int*)ei;
        s = p[e];
        d = p[N_EDGES + e];
    }
    s = min(max(s, 0), N_NODES - 1);
    d = min(max(d, 0), N_NODES - 1);
    g_esrc[e] = s;
    g_edst[e] = d;
    atomicAdd(&g_cnt[d], 1);
}

// ---------------- scan stage 1 (+ dinv fused) ----------------
__global__ void k_scan1() {
    __shared__ int sh[SCAN_B];
    int b = blockIdx.x, t = threadIdx.x;
    int i = b * SCAN_B + t;
    int v = (i < N_NODES) ? g_cnt[i] : 0;
    sh[t] = v;
    __syncthreads();
    for (int off = 1; off < SCAN_B; off <<= 1) {
        int add = (t >= off) ? sh[t - off] : 0;
        __syncthreads();
        sh[t] += add;
        __syncthreads();
    }
    if (i < N_NODES) {
        g_rowptr[i] = sh[t] - v;                       // block-local exclusive
        g_dinv[i]   = rsqrtf(1.0f + (float)v);         // +1 self-loop
    }
    if (t == SCAN_B - 1) g_blocksum[b] = sh[t];
}

// ---------------- scan stage 2: exclusive scan of block sums ----------------
__global__ void k_scan2() {
    __shared__ int sh[SCAN_B];
    int t = threadIdx.x;
    int v = (t < SCAN_NBLK) ? g_blocksum[t] : 0;
    sh[t] = v;
    __syncthreads();
    for (int off = 1; off < SCAN_B; off <<= 1) {
        int add = (t >= off) ? sh[t - off] : 0;
        __syncthreads();
        sh[t] += add;
        __syncthreads();
    }
    if (t < SCAN_NBLK) g_blocksum[t] = sh[t] - v;
}

// ---------------- CSR fill: dst-sorted packed (src, norm) -------------------
// global prefix = rowptr[d] + blocksum[d>>8]; no scan3 pass needed.
__global__ void k_fill() {
    int e = blockIdx.x * blockDim.x + threadIdx.x;
    if (e >= N_EDGES) return;
    int s = g_esrc[e];
    int d = g_edst[e];
    int pos = g_rowptr[d] + g_blocksum[d >> 8] + atomicAdd(&g_cur[d], 1);
    g_csr[pos] = make_int2(s, __float_as_int(g_dinv[s] * g_dinv[d]));
}

// ---------------- GEMM: h = xin @ W (64 rows/block, 4x4 register tile) ------
__global__ void k_gemm(int in_sel,
                       const float* __restrict__ x0,
                       const float* __restrict__ W) {
    const float* xin = (in_sel < 0) ? x0 : (const float*)selbuf(in_sel);

    __shared__ float Ws[64 * 64];
    __shared__ float xs[64 * 64];

    int tid = threadIdx.x;
    const float4* W4 = (const float4*)W;
    float4* Ws4 = (float4*)Ws;
    #pragma unroll
    for (int i = tid; i < 1024; i += 256) Ws4[i] = W4[i];

    int row0 = blockIdx.x * 64;
    const float4* x4 = (const float4*)xin;
    float4* xs4 = (float4*)xs;
    #pragma unroll
    for (int i = tid; i < 1024; i += 256) {
        int r = row0 + (i >> 4);
        xs4[i] = (r < N_NODES) ? x4[r * 16 + (i & 15)]
                               : make_float4(0.f, 0.f, 0.f, 0.f);
    }
    __syncthreads();

    int jc = (tid & 15) * 4;    // 4 output columns
    int rc = (tid >> 4) * 4;    // 4 rows

    float4 acc[4];
    #pragma unroll
    for (int r = 0; r < 4; r++) acc[r] = make_float4(0.f, 0.f, 0.f, 0.f);

    #pragma unroll
    for (int k4 = 0; k4 < 16; k4++) {
        float4 wv[4];
        #pragma unroll
        for (int kk = 0; kk < 4; kk++)
            wv[kk] = *(const float4*)&Ws[(k4 * 4 + kk) * 64 + jc];
        #pragma unroll
        for (int r = 0; r < 4; r++) {
            float4 a = *(const float4*)&xs[(rc + r) * 64 + k4 * 4];
            acc[r].x = fmaf(a.x, wv[0].x, acc[r].x);
            acc[r].y = fmaf(a.x, wv[0].y, acc[r].y);
            acc[r].z = fmaf(a.x, wv[0].z, acc[r].z);
            acc[r].w = fmaf(a.x, wv[0].w, acc[r].w);
            acc[r].x = fmaf(a.y, wv[1].x, acc[r].x);
            acc[r].y = fmaf(a.y, wv[1].y, acc[r].y);
            acc[r].z = fmaf(a.y, wv[1].z, acc[r].z);
            acc[r].w = fmaf(a.y, wv[1].w, acc[r].w);
            acc[r].x = fmaf(a.z, wv[2].x, acc[r].x);
            acc[r].y = fmaf(a.z, wv[2].y, acc[r].y);
            acc[r].z = fmaf(a.z, wv[2].z, acc[r].z);
            acc[r].w = fmaf(a.z, wv[2].w, acc[r].w);
            acc[r].x = fmaf(a.w, wv[3].x, acc[r].x);
            acc[r].y = fmaf(a.w, wv[3].y, acc[r].y);
            acc[r].z = fmaf(a.w, wv[3].z, acc[r].z);
            acc[r].w = fmaf(a.w, wv[3].w, acc[r].w);
        }
    }
    #pragma unroll
    for (int r = 0; r < 4; r++) {
        int row = row0 + rc + r;
        if (row < N_NODES) *(float4*)&g_h[row * 64 + jc] = acc[r];
    }
}

// ---------------- pull aggregation + fused mean ------------------------------
// 16 threads/node, float4 columns; warp covers 2 nodes (loop to warp-max len).
__global__ void k_aggr(int out_sel, int layer, const float4* __restrict__ b4p) {
    int id   = blockIdx.x * 256 + threadIdx.x;
    int node = id >> 4;
    int c4   = id & 15;
    const float4* h4   = (const float4*)g_h;
    float4*       out4 = (float4*)selbuf(out_sel);

    float di = g_dinv[node];
    float sl = di * di;
    float4 acc = h4[node * 16 + c4];          // self-loop message
    acc.x *= sl; acc.y *= sl; acc.z *= sl; acc.w *= sl;

    int beg = g_rowptr[node] + g_blocksum[node >> 8];
    int end = (node == N_NODES - 1)
                ? N_EDGES
                : (g_rowptr[node + 1] + g_blocksum[(node + 1) >> 8]);
    int len = end - beg;
    int m   = max(len, __shfl_xor_sync(0xffffffffu, len, 16));

    for (int j = 0; j < m; j += 2) {
        int2 e0, e1;
        float4 v0, v1;
        bool p0 = (j < len), p1 = (j + 1 < len);
        if (p0) e0 = __ldg(&g_csr[beg + j]);
        if (p1) e1 = __ldg(&g_csr[beg + j + 1]);
        if (p0) v0 = __ldg(&h4[e0.x * 16 + c4]);
        if (p1) v1 = __ldg(&h4[e1.x * 16 + c4]);
        if (p0) {
            float n = __int_as_float(e0.y);
            acc.x += v0.x * n; acc.y += v0.y * n;
            acc.z += v0.z * n; acc.w += v0.w * n;
        }
        if (p1) {
            float n = __int_as_float(e1.y);
            acc.x += v1.x * n; acc.y += v1.y * n;
            acc.z += v1.z * n; acc.w += v1.w * n;
        }
    }
    float4 bv = __ldg(&b4p[c4]);
    acc.x += bv.x; acc.y += bv.y; acc.z += bv.z; acc.w += bv.w;
    out4[node * 16 + c4] = acc;

    // fused column-mean: block reduce 16 nodes, spread-atomic to scratch
    __shared__ float4 sh[256];
    int t = threadIdx.x;
    sh[t] = acc;
    __syncthreads();
    if (t < 128) { sh[t].x += sh[t+128].x; sh[t].y += sh[t+128].y;
                   sh[t].z += sh[t+128].z; sh[t].w += sh[t+128].w; }
    __syncthreads();
    if (t < 64)  { sh[t].x += sh[t+64].x; sh[t].y += sh[t+64].y;
                   sh[t].z += sh[t+64].z; sh[t].w += sh[t+64].w; }
    __syncthreads();
    if (t < 32)  { sh[t].x += sh[t+32].x; sh[t].y += sh[t+32].y;
                   sh[t].z += sh[t+32].z; sh[t].w += sh[t+32].w; }
    __syncthreads();
    if (t < 16) {
        float4 s = sh[t];
        s.x += sh[t+16].x; s.y += sh[t+16].y; s.z += sh[t+16].z; s.w += sh[t+16].w;
        float* gp = &g_meanacc[(layer * MEAN_SPREAD + (blockIdx.x & (MEAN_SPREAD - 1))) * D + t * 4];
        atomicAdd(&gp[0], s.x);
        atomicAdd(&gp[1], s.y);
        atomicAdd(&gp[2], s.z);
        atomicAdd(&gp[3], s.w);
    }
}

// ---------------- finish: reduce mean buckets for all 4 layers ----------------
__global__ void k_finish(float* __restrict__ out) {
    int t = threadIdx.x;          // 256 threads: layer = t>>6, col = t&63
    int layer = t >> 6;
    int c = t & 63;
    float s = 0.f;
    #pragma unroll
    for (int k = 0; k < MEAN_SPREAD; k++)
        s += g_meanacc[(layer * MEAN_SPREAD + k) * D + c];
    out[layer * D + c] = s * (1.0f / (float)N_NODES);
}

// ---------------- launch ----------------
extern "C" void kernel_launch(void* const* d_in, const int* in_sizes, int n_in,
                              void* d_out, int out_size) {
    const float* x   = (const float*)d_in[0];
    const void*  ei  = d_in[1];
    float*       out = (float*)d_out;

    k_zero  <<<(N_NODES + 255) / 256, 256>>>((const int*)ei);
    k_edges <<<(N_EDGES + 255) / 256, 256>>>(ei);
    k_scan1 <<<SCAN_NBLK, SCAN_B>>>();
    k_scan2 <<<1, SCAN_B>>>();
    k_fill  <<<(N_EDGES + 255) / 256, 256>>>();

    for (int l = 0; l < 4; l++) {
        int in_sel  = (l == 0) ? -1 : ((l - 1) & 1);
        int out_sel = l & 1;
        const float* W = (const float*)d_in[2 + 2 * l];
        const float* b = (const float*)d_in[3 + 2 * l];
        k_gemm<<<(N_NODES + 63) / 64, 256>>>(in_sel, x, W);
        k_aggr<<<(N_NODES * 16) / 256, 256>>>(out_sel, l, (const float4*)b);
    }
    k_finish<<<1, 256>>>(out);
}